// round 12
// baseline (speedup 1.0000x reference)
#include <cuda_runtime.h>
#include <cuda_fp16.h>

// Geometry: [B=2, C=1, D=160, H=192, W=160] fp32.
#define Bsz 2
#define Dd  160
#define Hh  192
#define Ww  160
#define HW  (Hh * Ww)
#define DHW (Dd * HW)
#define NTOT (Bsz * DHW)
#define INV_V (1.0f / 729.0f)
#define EPSL 1e-6f

// WH tiling: full W rows, CHO output H-rows (+8 halo), padded row stride.
#define CHO 48
#define CHH 56          // CHO + 8
#define RSTR 168        // 4 + 160 + 4
#define NT1 640         // blockDim (160, 4)

#define CD2 10          // D-chunk for column kernels (1920 blocks)

// Half intermediates: [0]=St/SA [1]=Sp/SB [2..3]=interleaved (tc,pc) pairs
// [4]=SC.  98.3 MB static scratch.
__device__ __half g_h[5][NTOT];

__device__ __forceinline__ int clampi(int v, int lo, int hi) {
    return min(max(v, lo), hi);
}

// ===========================================================================
// K1: per-plane W+H 9x9 box sums of t and p -> g_h[0], g_h[1] (fp16).
// Also zeroes the output scalar. smem: sIn[56][168] + sW[56][160] = 73472 B.
// ===========================================================================
__global__ __launch_bounds__(NT1, 3)
void k_wh2(const float* __restrict__ t, const float* __restrict__ p,
           float* __restrict__ out) {
    extern __shared__ float sm[];
    float* sIn = sm;
    float* sW  = sm + CHH * RSTR;

    const int tx = threadIdx.x, ty = threadIdx.y;
    const int tid = ty * 160 + tx;
    if (blockIdx.x == 0 && blockIdx.y == 0 && blockIdx.z == 0 && tid == 0)
        *out = 0.f;
    const int h0c = blockIdx.x * CHO;
    const long pl = (long)blockIdx.z * DHW + (long)blockIdx.y * HW;

    for (int f = 0; f < 2; ++f) {
        const float* __restrict__ src = f ? p : t;
        __half* __restrict__ dst = g_h[f];
        for (int u = tid; u < CHH * 40; u += NT1) {
            int row = u / 40, c4 = u % 40;
            int gh = clampi(h0c - 4 + row, 0, Hh - 1);
            float4 v = *(const float4*)(src + pl + (long)gh * Ww + c4 * 4);
            *(float4*)(sIn + row * RSTR + 4 + c4 * 4) = v;
        }
        if (tid < CHH * 2) {
            int row = tid >> 1, side = tid & 1;
            int gh = clampi(h0c - 4 + row, 0, Hh - 1);
            float v = src[pl + (long)gh * Ww + (side ? Ww - 1 : 0)];
            float* e = sIn + row * RSTR + (side ? 164 : 0);
            e[0] = v; e[1] = v; e[2] = v; e[3] = v;
        }
        __syncthreads();
        for (int u = tid; u < CHH * 40; u += NT1) {
            int row = u / 40, s = u % 40;
            const float* rp = sIn + row * RSTR + 4 * s;
            float4 x0 = *(const float4*)rp;
            float4 x1 = *(const float4*)(rp + 4);
            float4 x2 = *(const float4*)(rp + 8);
            float s0 = x0.x + x0.y + x0.z + x0.w + x1.x + x1.y + x1.z + x1.w + x2.x;
            float s1 = s0 - x0.x + x2.y;
            float s2 = s1 - x0.y + x2.z;
            float s3 = s2 - x0.z + x2.w;
            *(float4*)(sW + row * 160 + 4 * s) = make_float4(s0, s1, s2, s3);
        }
        __syncthreads();
        {
            const int r0 = ty * 12;
            const float* c = sW + tx;
            float s = c[(r0 + 0) * 160] + c[(r0 + 1) * 160] + c[(r0 + 2) * 160]
                    + c[(r0 + 3) * 160] + c[(r0 + 4) * 160] + c[(r0 + 5) * 160]
                    + c[(r0 + 6) * 160] + c[(r0 + 7) * 160] + c[(r0 + 8) * 160];
            __half* o = dst + pl + (long)(h0c + r0) * Ww + tx;
            o[0] = __float2half_rn(s);
#pragma unroll
            for (int k = 1; k < 12; ++k) {
                s += c[(r0 + k + 8) * 160] - c[(r0 + k - 1) * 160];
                o[(long)k * Ww] = __float2half_rn(s);
            }
        }
        __syncthreads();
    }
}

// ===========================================================================
// K2: D-axis running box sum of St,Sp in HALF2 arithmetic -> means; fused
// centering. Thread = 4 adjacent columns; peeled first plane + unrolled loop.
// Writes INTERLEAVED (tc,pc) half2 pairs (one uint4 per 4 voxels).
// grid (HW/512, D/CD2, B) = (60, 16, 2) = 1920 blocks of 128.
// ===========================================================================
__global__ __launch_bounds__(128, 8)
void k_dcenter(const float* __restrict__ t, const float* __restrict__ p) {
    const int b = blockIdx.z;
    const int hw = (blockIdx.x * 128 + threadIdx.x) * 4;
    const int d0 = blockIdx.y * CD2;
    const __half* __restrict__ St = g_h[0];
    const __half* __restrict__ Sp = g_h[1];
    __half2* __restrict__ Pair = (__half2*)g_h[2];   // [NTOT] pairs (tc,pc)
    const long base = (long)b * DHW + hw;

    __half2 sa0 = __float2half2_rn(0.f), sa1 = sa0, sb0 = sa0, sb1 = sa0;
#pragma unroll
    for (int j = -4; j <= 4; ++j) {
        long a = base + (long)clampi(d0 + j, 0, Dd - 1) * HW;
        uint2 ua = *(const uint2*)(St + a);
        uint2 ub = *(const uint2*)(Sp + a);
        sa0 = __hadd2(sa0, *reinterpret_cast<__half2*>(&ua.x));
        sa1 = __hadd2(sa1, *reinterpret_cast<__half2*>(&ua.y));
        sb0 = __hadd2(sb0, *reinterpret_cast<__half2*>(&ub.x));
        sb1 = __hadd2(sb1, *reinterpret_cast<__half2*>(&ub.y));
    }
    const __half2 invv = __float2half2_rn(INV_V);
    {   // emit plane d0
        long a = base + (long)d0 * HW;
        float4 vt = *(const float4*)(t + a);
        float4 vp = *(const float4*)(p + a);
        __half2 t0 = __floats2half2_rn(vt.x, vt.y), t1 = __floats2half2_rn(vt.z, vt.w);
        __half2 u0 = __floats2half2_rn(vp.x, vp.y), u1 = __floats2half2_rn(vp.z, vp.w);
        __half2 tc0 = __hsub2(t0, __hmul2(sa0, invv));
        __half2 tc1 = __hsub2(t1, __hmul2(sa1, invv));
        __half2 pc0 = __hsub2(u0, __hmul2(sb0, invv));
        __half2 pc1 = __hsub2(u1, __hmul2(sb1, invv));
        __half2 q0 = __lows2half2(tc0, pc0), q1 = __highs2half2(tc0, pc0);
        __half2 q2 = __lows2half2(tc1, pc1), q3 = __highs2half2(tc1, pc1);
        uint4 u;
        u.x = *(unsigned*)&q0; u.y = *(unsigned*)&q1;
        u.z = *(unsigned*)&q2; u.w = *(unsigned*)&q3;
        *(uint4*)(Pair + a) = u;
    }
#pragma unroll
    for (int d = d0 + 1; d < d0 + CD2; ++d) {
        long ap = base + (long)min(d + 4, Dd - 1) * HW;
        long am = base + (long)max(d - 5, 0) * HW;
        uint2 uap = *(const uint2*)(St + ap), uam = *(const uint2*)(St + am);
        uint2 ubp = *(const uint2*)(Sp + ap), ubm = *(const uint2*)(Sp + am);
        sa0 = __hadd2(sa0, __hsub2(*reinterpret_cast<__half2*>(&uap.x),
                                   *reinterpret_cast<__half2*>(&uam.x)));
        sa1 = __hadd2(sa1, __hsub2(*reinterpret_cast<__half2*>(&uap.y),
                                   *reinterpret_cast<__half2*>(&uam.y)));
        sb0 = __hadd2(sb0, __hsub2(*reinterpret_cast<__half2*>(&ubp.x),
                                   *reinterpret_cast<__half2*>(&ubm.x)));
        sb1 = __hadd2(sb1, __hsub2(*reinterpret_cast<__half2*>(&ubp.y),
                                   *reinterpret_cast<__half2*>(&ubm.y)));
        long a = base + (long)d * HW;
        float4 vt = *(const float4*)(t + a);
        float4 vp = *(const float4*)(p + a);
        __half2 t0 = __floats2half2_rn(vt.x, vt.y), t1 = __floats2half2_rn(vt.z, vt.w);
        __half2 u0 = __floats2half2_rn(vp.x, vp.y), u1 = __floats2half2_rn(vp.z, vp.w);
        __half2 tc0 = __hsub2(t0, __hmul2(sa0, invv));
        __half2 tc1 = __hsub2(t1, __hmul2(sa1, invv));
        __half2 pc0 = __hsub2(u0, __hmul2(sb0, invv));
        __half2 pc1 = __hsub2(u1, __hmul2(sb1, invv));
        __half2 q0 = __lows2half2(tc0, pc0), q1 = __highs2half2(tc0, pc0);
        __half2 q2 = __lows2half2(tc1, pc1), q3 = __highs2half2(tc1, pc1);
        uint4 u;
        u.x = *(unsigned*)&q0; u.y = *(unsigned*)&q1;
        u.z = *(unsigned*)&q2; u.w = *(unsigned*)&q3;
        *(uint4*)(Pair + a) = u;
    }
}

// ===========================================================================
// K3: per-plane W+H box sums of (tc*pc, tc^2, pc^2) from interleaved pairs.
// smem: sCt/sCp half[56][168] + sW fp32[56][160] = 73472 B.
// ===========================================================================
__global__ __launch_bounds__(NT1, 3)
void k_prodwh() {
    extern __shared__ float sm[];
    __half* sCt = (__half*)sm;
    __half* sCp = sCt + CHH * RSTR;
    float*  sW  = sm + (2 * CHH * RSTR) / 2;

    const int tx = threadIdx.x, ty = threadIdx.y;
    const int tid = ty * 160 + tx;
    const int h0c = blockIdx.x * CHO;
    const long pl = (long)blockIdx.z * DHW + (long)blockIdx.y * HW;
    const __half2* __restrict__ Pair = (const __half2*)g_h[2];

    // ---- load interleaved pairs, deinterleave into smem ----
    for (int u = tid; u < CHH * 40; u += NT1) {
        int row = u / 40, c4 = u % 40;
        int gh = clampi(h0c - 4 + row, 0, Hh - 1);
        const long a = pl + (long)gh * Ww + c4 * 4;   // 4 voxels
        uint4 uu = *(const uint4*)(Pair + a);
        __half2 q0 = *reinterpret_cast<__half2*>(&uu.x);
        __half2 q1 = *reinterpret_cast<__half2*>(&uu.y);
        __half2 q2 = *reinterpret_cast<__half2*>(&uu.z);
        __half2 q3 = *reinterpret_cast<__half2*>(&uu.w);
        __half2 t01 = __lows2half2(q0, q1),  t23 = __lows2half2(q2, q3);
        __half2 p01 = __highs2half2(q0, q1), p23 = __highs2half2(q2, q3);
        uint2 ut, up;
        ut.x = *(unsigned*)&t01; ut.y = *(unsigned*)&t23;
        up.x = *(unsigned*)&p01; up.y = *(unsigned*)&p23;
        *(uint2*)(sCt + row * RSTR + 4 + c4 * 4) = ut;
        *(uint2*)(sCp + row * RSTR + 4 + c4 * 4) = up;
    }
    if (tid < CHH * 2) {
        int row = tid >> 1, side = tid & 1;
        int gh = clampi(h0c - 4 + row, 0, Hh - 1);
        const long a = pl + (long)gh * Ww + (side ? Ww - 1 : 0);
        __half2 q = Pair[a];
        __half vt = __low2half(q), vp = __high2half(q);
        __half* e0 = sCt + row * RSTR + (side ? 164 : 0);
        __half* e1 = sCp + row * RSTR + (side ? 164 : 0);
        e0[0] = vt; e0[1] = vt; e0[2] = vt; e0[3] = vt;
        e1[0] = vp; e1[1] = vp; e1[2] = vp; e1[3] = vp;
    }
    __syncthreads();

#pragma unroll
    for (int q = 0; q < 3; ++q) {
        __half* __restrict__ dst = g_h[q == 0 ? 0 : (q == 1 ? 1 : 4)];
        for (int u = tid; u < CHH * 40; u += NT1) {
            int row = u / 40, s = u % 40;
            const __half* ra = (q == 2 ? sCp : sCt) + row * RSTR + 4 * s;
            const __half* rb = (q == 1 ? sCt : sCp) + row * RSTR + 4 * s;
            float2 a01 = __half22float2(*(const __half2*)(ra));
            float2 a23 = __half22float2(*(const __half2*)(ra + 2));
            float2 a45 = __half22float2(*(const __half2*)(ra + 4));
            float2 a67 = __half22float2(*(const __half2*)(ra + 6));
            float2 a89 = __half22float2(*(const __half2*)(ra + 8));
            float2 aAB = __half22float2(*(const __half2*)(ra + 10));
            float2 b01 = __half22float2(*(const __half2*)(rb));
            float2 b23 = __half22float2(*(const __half2*)(rb + 2));
            float2 b45 = __half22float2(*(const __half2*)(rb + 4));
            float2 b67 = __half22float2(*(const __half2*)(rb + 6));
            float2 b89 = __half22float2(*(const __half2*)(rb + 8));
            float2 bAB = __half22float2(*(const __half2*)(rb + 10));
            float v0 = a01.x * b01.x, v1 = a01.y * b01.y;
            float v2 = a23.x * b23.x, v3 = a23.y * b23.y;
            float v4 = a45.x * b45.x, v5 = a45.y * b45.y;
            float v6 = a67.x * b67.x, v7 = a67.y * b67.y;
            float v8 = a89.x * b89.x, v9 = a89.y * b89.y;
            float v10 = aAB.x * bAB.x, v11 = aAB.y * bAB.y;
            float s0 = v0 + v1 + v2 + v3 + v4 + v5 + v6 + v7 + v8;
            float s1 = s0 - v0 + v9;
            float s2 = s1 - v1 + v10;
            float s3 = s2 - v2 + v11;
            *(float4*)(sW + row * 160 + 4 * s) = make_float4(s0, s1, s2, s3);
        }
        __syncthreads();
        {
            const int r0 = ty * 12;
            const float* c = sW + tx;
            float s = c[(r0 + 0) * 160] + c[(r0 + 1) * 160] + c[(r0 + 2) * 160]
                    + c[(r0 + 3) * 160] + c[(r0 + 4) * 160] + c[(r0 + 5) * 160]
                    + c[(r0 + 6) * 160] + c[(r0 + 7) * 160] + c[(r0 + 8) * 160];
            __half* o = dst + pl + (long)(h0c + r0) * Ww + tx;
            o[0] = __float2half_rn(s);
#pragma unroll
            for (int k = 1; k < 12; ++k) {
                s += c[(r0 + k + 8) * 160] - c[(r0 + k - 1) * 160];
                o[(long)k * Ww] = __float2half_rn(s);
            }
        }
        __syncthreads();
    }
}

// ===========================================================================
// K4: D-axis running box sums of SA,SB,SC in HALF2 arithmetic + cc (fp32) +
// mean reduction. 4 columns/thread. grid (60, 16, 2) = 1920 blocks of 128.
// ===========================================================================
__global__ __launch_bounds__(128, 8)
void k_d3cc(float* __restrict__ out) {
    const int b = blockIdx.z;
    const int hw = (blockIdx.x * 128 + threadIdx.x) * 4;
    const int d0 = blockIdx.y * CD2;
    const __half* __restrict__ A = g_h[0];
    const __half* __restrict__ B = g_h[1];
    const __half* __restrict__ C = g_h[4];
    const long base = (long)b * DHW + hw;

    __half2 sa0 = __float2half2_rn(0.f), sa1 = sa0;
    __half2 sb0 = sa0, sb1 = sa0, sc0 = sa0, sc1 = sa0;
#pragma unroll
    for (int j = -4; j <= 4; ++j) {
        long a = base + (long)clampi(d0 + j, 0, Dd - 1) * HW;
        uint2 ua = *(const uint2*)(A + a);
        uint2 ub = *(const uint2*)(B + a);
        uint2 uc = *(const uint2*)(C + a);
        sa0 = __hadd2(sa0, *reinterpret_cast<__half2*>(&ua.x));
        sa1 = __hadd2(sa1, *reinterpret_cast<__half2*>(&ua.y));
        sb0 = __hadd2(sb0, *reinterpret_cast<__half2*>(&ub.x));
        sb1 = __hadd2(sb1, *reinterpret_cast<__half2*>(&ub.y));
        sc0 = __hadd2(sc0, *reinterpret_cast<__half2*>(&uc.x));
        sc1 = __hadd2(sc1, *reinterpret_cast<__half2*>(&uc.y));
    }
    float acc;
    {
        float2 fa0 = __half22float2(sa0), fa1 = __half22float2(sa1);
        float2 fb0 = __half22float2(sb0), fb1 = __half22float2(sb1);
        float2 fc0 = __half22float2(sc0), fc1 = __half22float2(sc1);
        acc = fminf(fmaxf(__fdividef(fa0.x * fa0.x + EPSL, fb0.x * fc0.x + EPSL), 0.f), 1.f)
            + fminf(fmaxf(__fdividef(fa0.y * fa0.y + EPSL, fb0.y * fc0.y + EPSL), 0.f), 1.f)
            + fminf(fmaxf(__fdividef(fa1.x * fa1.x + EPSL, fb1.x * fc1.x + EPSL), 0.f), 1.f)
            + fminf(fmaxf(__fdividef(fa1.y * fa1.y + EPSL, fb1.y * fc1.y + EPSL), 0.f), 1.f);
    }
#pragma unroll
    for (int d = d0 + 1; d < d0 + CD2; ++d) {
        long ap = base + (long)min(d + 4, Dd - 1) * HW;
        long am = base + (long)max(d - 5, 0) * HW;
        uint2 uap = *(const uint2*)(A + ap), uam = *(const uint2*)(A + am);
        uint2 ubp = *(const uint2*)(B + ap), ubm = *(const uint2*)(B + am);
        uint2 ucp = *(const uint2*)(C + ap), ucm = *(const uint2*)(C + am);
        sa0 = __hadd2(sa0, __hsub2(*reinterpret_cast<__half2*>(&uap.x),
                                   *reinterpret_cast<__half2*>(&uam.x)));
        sa1 = __hadd2(sa1, __hsub2(*reinterpret_cast<__half2*>(&uap.y),
                                   *reinterpret_cast<__half2*>(&uam.y)));
        sb0 = __hadd2(sb0, __hsub2(*reinterpret_cast<__half2*>(&ubp.x),
                                   *reinterpret_cast<__half2*>(&ubm.x)));
        sb1 = __hadd2(sb1, __hsub2(*reinterpret_cast<__half2*>(&ubp.y),
                                   *reinterpret_cast<__half2*>(&ubm.y)));
        sc0 = __hadd2(sc0, __hsub2(*reinterpret_cast<__half2*>(&ucp.x),
                                   *reinterpret_cast<__half2*>(&ucm.x)));
        sc1 = __hadd2(sc1, __hsub2(*reinterpret_cast<__half2*>(&ucp.y),
                                   *reinterpret_cast<__half2*>(&ucm.y)));
        float2 fa0 = __half22float2(sa0), fa1 = __half22float2(sa1);
        float2 fb0 = __half22float2(sb0), fb1 = __half22float2(sb1);
        float2 fc0 = __half22float2(sc0), fc1 = __half22float2(sc1);
        acc += fminf(fmaxf(__fdividef(fa0.x * fa0.x + EPSL, fb0.x * fc0.x + EPSL), 0.f), 1.f)
             + fminf(fmaxf(__fdividef(fa0.y * fa0.y + EPSL, fb0.y * fc0.y + EPSL), 0.f), 1.f)
             + fminf(fmaxf(__fdividef(fa1.x * fa1.x + EPSL, fb1.x * fc1.x + EPSL), 0.f), 1.f)
             + fminf(fmaxf(__fdividef(fa1.y * fa1.y + EPSL, fb1.y * fc1.y + EPSL), 0.f), 1.f);
    }

    __shared__ float red[128];
    red[threadIdx.x] = acc;
    __syncthreads();
#pragma unroll
    for (int s = 64; s > 0; s >>= 1) {
        if (threadIdx.x < s) red[threadIdx.x] += red[threadIdx.x + s];
        __syncthreads();
    }
    if (threadIdx.x == 0) atomicAdd(out, -red[0] * (1.0f / (float)NTOT));
}

// ===========================================================================
extern "C" void kernel_launch(void* const* d_in, const int* in_sizes, int n_in,
                              void* d_out, int out_size) {
    const float* t = (const float*)d_in[0];  // y_true
    const float* p = (const float*)d_in[1];  // y_pred
    float* out = (float*)d_out;

    static const int SMWH = (CHH * RSTR + CHH * 160) * 4;   // 73472 B
    cudaFuncSetAttribute(k_wh2,    cudaFuncAttributeMaxDynamicSharedMemorySize, SMWH);
    cudaFuncSetAttribute(k_prodwh, cudaFuncAttributeMaxDynamicSharedMemorySize, SMWH);

    const dim3 bwh(160, 4);
    const dim3 gwh(Hh / CHO, Dd, Bsz);               // (4, 160, 2)
    const dim3 gcol(HW / 512, Dd / CD2, Bsz);        // (60, 16, 2) = 1920 blocks

    k_wh2<<<gwh, bwh, SMWH>>>(t, p, out);
    k_dcenter<<<gcol, 128>>>(t, p);
    k_prodwh<<<gwh, bwh, SMWH>>>();
    k_d3cc<<<gcol, 128>>>(out);
}

// round 13
// speedup vs baseline: 1.0272x; 1.0272x over previous
#include <cuda_runtime.h>
#include <cuda_fp16.h>

// Geometry: [B=2, C=1, D=160, H=192, W=160] fp32.
#define Bsz 2
#define Dd  160
#define Hh  192
#define Ww  160
#define HW  (Hh * Ww)
#define DHW (Dd * HW)
#define NTOT (Bsz * DHW)
#define INV_V (1.0f / 729.0f)
#define EPSL 1e-6f

// WH tiling: full W rows, CHO output H-rows (+8 halo), padded row stride.
#define CHO 48
#define CHH 56          // CHO + 8
#define RSTR 168        // 4 + 160 + 4
#define NT1 640         // blockDim (160, 4)

#define CD2 20          // D-chunk for column kernels (960 blocks) — R11 optimum

// Half intermediates: [0..1]=interleaved (St,Sp) sum pairs, later SA/SB;
// [2..3]=interleaved (tc,pc) pairs; [4]=SC.  98.3 MB static scratch.
__device__ __half g_h[5][NTOT];

__device__ __forceinline__ int clampi(int v, int lo, int hi) {
    return min(max(v, lo), hi);
}

// ===========================================================================
// K1: per-plane W+H 9x9 box sums of (t,p) carried as interleaved half2 pairs.
// One load phase, one W-pass, one H-pass for BOTH fields. Output: paired
// (St,Sp) half2 stream in g_h[0..1]. Also zeroes the output scalar.
// smem: sIn half2[56][168] (37632 B) + sW half2[56][160] (35840 B) = 73472 B.
// ===========================================================================
__global__ __launch_bounds__(NT1, 3)
void k_wh2(const float* __restrict__ t, const float* __restrict__ p,
           float* __restrict__ out) {
    extern __shared__ float sm[];
    __half2* sIn = (__half2*)sm;                 // (t,p) pairs, padded rows
    __half2* sW  = sIn + CHH * RSTR;             // (Wt,Wp) strip-sum pairs

    const int tx = threadIdx.x, ty = threadIdx.y;
    const int tid = ty * 160 + tx;
    if (blockIdx.x == 0 && blockIdx.y == 0 && blockIdx.z == 0 && tid == 0)
        *out = 0.f;
    const int h0c = blockIdx.x * CHO;
    const long pl = (long)blockIdx.z * DHW + (long)blockIdx.y * HW;
    __half2* __restrict__ SumPair = (__half2*)g_h[0];

    // ---- load both fields as pairs ----
    for (int u = tid; u < CHH * 40; u += NT1) {
        int row = u / 40, c4 = u % 40;
        int gh = clampi(h0c - 4 + row, 0, Hh - 1);
        const long a = pl + (long)gh * Ww + c4 * 4;
        float4 vt = *(const float4*)(t + a);
        float4 vp = *(const float4*)(p + a);
        __half2 q0 = __floats2half2_rn(vt.x, vp.x);
        __half2 q1 = __floats2half2_rn(vt.y, vp.y);
        __half2 q2 = __floats2half2_rn(vt.z, vp.z);
        __half2 q3 = __floats2half2_rn(vt.w, vp.w);
        uint4 u4;
        u4.x = *(unsigned*)&q0; u4.y = *(unsigned*)&q1;
        u4.z = *(unsigned*)&q2; u4.w = *(unsigned*)&q3;
        *(uint4*)(sIn + row * RSTR + 4 + c4 * 4) = u4;
    }
    if (tid < CHH * 2) {
        int row = tid >> 1, side = tid & 1;
        int gh = clampi(h0c - 4 + row, 0, Hh - 1);
        const long a = pl + (long)gh * Ww + (side ? Ww - 1 : 0);
        __half2 q = __floats2half2_rn(t[a], p[a]);
        __half2* e = sIn + row * RSTR + (side ? 164 : 0);
        e[0] = q; e[1] = q; e[2] = q; e[3] = q;
    }
    __syncthreads();

    // ---- W: 9-tap running strip sums for both fields (fp32 math) ----
    for (int u = tid; u < CHH * 40; u += NT1) {
        int row = u / 40, s = u % 40;
        const __half2* rp = sIn + row * RSTR + 4 * s;
        uint4 x0 = *(const uint4*)(rp);
        uint4 x1 = *(const uint4*)(rp + 4);
        uint4 x2 = *(const uint4*)(rp + 8);
        float2 f0 = __half22float2(*reinterpret_cast<__half2*>(&x0.x));
        float2 f1 = __half22float2(*reinterpret_cast<__half2*>(&x0.y));
        float2 f2 = __half22float2(*reinterpret_cast<__half2*>(&x0.z));
        float2 f3 = __half22float2(*reinterpret_cast<__half2*>(&x0.w));
        float2 f4 = __half22float2(*reinterpret_cast<__half2*>(&x1.x));
        float2 f5 = __half22float2(*reinterpret_cast<__half2*>(&x1.y));
        float2 f6 = __half22float2(*reinterpret_cast<__half2*>(&x1.z));
        float2 f7 = __half22float2(*reinterpret_cast<__half2*>(&x1.w));
        float2 f8 = __half22float2(*reinterpret_cast<__half2*>(&x2.x));
        float2 f9 = __half22float2(*reinterpret_cast<__half2*>(&x2.y));
        float2 fA = __half22float2(*reinterpret_cast<__half2*>(&x2.z));
        float2 fB = __half22float2(*reinterpret_cast<__half2*>(&x2.w));
        float2 s0, s1, s2, s3;
        s0.x = f0.x + f1.x + f2.x + f3.x + f4.x + f5.x + f6.x + f7.x + f8.x;
        s0.y = f0.y + f1.y + f2.y + f3.y + f4.y + f5.y + f6.y + f7.y + f8.y;
        s1.x = s0.x - f0.x + f9.x;  s1.y = s0.y - f0.y + f9.y;
        s2.x = s1.x - f1.x + fA.x;  s2.y = s1.y - f1.y + fA.y;
        s3.x = s2.x - f2.x + fB.x;  s3.y = s2.y - f2.y + fB.y;
        __half2 w0 = __floats2half2_rn(s0.x, s0.y);
        __half2 w1 = __floats2half2_rn(s1.x, s1.y);
        __half2 w2 = __floats2half2_rn(s2.x, s2.y);
        __half2 w3 = __floats2half2_rn(s3.x, s3.y);
        uint4 u4;
        u4.x = *(unsigned*)&w0; u4.y = *(unsigned*)&w1;
        u4.z = *(unsigned*)&w2; u4.w = *(unsigned*)&w3;
        *(uint4*)(sW + row * 160 + 4 * s) = u4;
    }
    __syncthreads();

    // ---- H: running sums (fp32) over 12-row groups, store pairs ----
    {
        const int r0 = ty * 12;
        const __half2* c = sW + tx;
        float2 s = make_float2(0.f, 0.f);
#pragma unroll
        for (int k = 0; k < 9; ++k) {
            float2 f = __half22float2(c[(r0 + k) * 160]);
            s.x += f.x; s.y += f.y;
        }
        __half2* o = SumPair + pl + (long)(h0c + r0) * Ww + tx;
        o[0] = __floats2half2_rn(s.x, s.y);
#pragma unroll
        for (int k = 1; k < 12; ++k) {
            float2 fp2 = __half22float2(c[(r0 + k + 8) * 160]);
            float2 fm2 = __half22float2(c[(r0 + k - 1) * 160]);
            s.x += fp2.x - fm2.x; s.y += fp2.y - fm2.y;
            o[(long)k * Ww] = __floats2half2_rn(s.x, s.y);
        }
    }
}

// ===========================================================================
// K2: D-axis running box sum of the (St,Sp) pair stream in half2 arithmetic;
// fused centering -> interleaved (tc,pc) pairs. 4 columns/thread, peeled
// first plane + unroll-4 loop. grid (60, 8, 2) = 960 blocks of 128.
// ===========================================================================
__global__ __launch_bounds__(128, 8)
void k_dcenter(const float* __restrict__ t, const float* __restrict__ p) {
    const int b = blockIdx.z;
    const int hw = (blockIdx.x * 128 + threadIdx.x) * 4;
    const int d0 = blockIdx.y * CD2;
    const __half2* __restrict__ Sum = (const __half2*)g_h[0];
    __half2* __restrict__ Pair = (__half2*)g_h[2];
    const long base = (long)b * DHW + hw;

    __half2 s0 = __float2half2_rn(0.f), s1 = s0, s2 = s0, s3 = s0;
#pragma unroll
    for (int j = -4; j <= 4; ++j) {
        long a = base + (long)clampi(d0 + j, 0, Dd - 1) * HW;
        uint4 u = *(const uint4*)(Sum + a);
        s0 = __hadd2(s0, *reinterpret_cast<__half2*>(&u.x));
        s1 = __hadd2(s1, *reinterpret_cast<__half2*>(&u.y));
        s2 = __hadd2(s2, *reinterpret_cast<__half2*>(&u.z));
        s3 = __hadd2(s3, *reinterpret_cast<__half2*>(&u.w));
    }
    const __half2 invv = __float2half2_rn(INV_V);
    {   // emit plane d0
        long a = base + (long)d0 * HW;
        float4 vt = *(const float4*)(t + a);
        float4 vp = *(const float4*)(p + a);
        __half2 q0 = __hsub2(__floats2half2_rn(vt.x, vp.x), __hmul2(s0, invv));
        __half2 q1 = __hsub2(__floats2half2_rn(vt.y, vp.y), __hmul2(s1, invv));
        __half2 q2 = __hsub2(__floats2half2_rn(vt.z, vp.z), __hmul2(s2, invv));
        __half2 q3 = __hsub2(__floats2half2_rn(vt.w, vp.w), __hmul2(s3, invv));
        uint4 u;
        u.x = *(unsigned*)&q0; u.y = *(unsigned*)&q1;
        u.z = *(unsigned*)&q2; u.w = *(unsigned*)&q3;
        *(uint4*)(Pair + a) = u;
    }
#pragma unroll 4
    for (int d = d0 + 1; d < d0 + CD2; ++d) {
        long ap = base + (long)min(d + 4, Dd - 1) * HW;
        long am = base + (long)max(d - 5, 0) * HW;
        uint4 ue = *(const uint4*)(Sum + ap);
        uint4 ul = *(const uint4*)(Sum + am);
        s0 = __hadd2(s0, __hsub2(*reinterpret_cast<__half2*>(&ue.x),
                                 *reinterpret_cast<__half2*>(&ul.x)));
        s1 = __hadd2(s1, __hsub2(*reinterpret_cast<__half2*>(&ue.y),
                                 *reinterpret_cast<__half2*>(&ul.y)));
        s2 = __hadd2(s2, __hsub2(*reinterpret_cast<__half2*>(&ue.z),
                                 *reinterpret_cast<__half2*>(&ul.z)));
        s3 = __hadd2(s3, __hsub2(*reinterpret_cast<__half2*>(&ue.w),
                                 *reinterpret_cast<__half2*>(&ul.w)));
        long a = base + (long)d * HW;
        float4 vt = *(const float4*)(t + a);
        float4 vp = *(const float4*)(p + a);
        __half2 q0 = __hsub2(__floats2half2_rn(vt.x, vp.x), __hmul2(s0, invv));
        __half2 q1 = __hsub2(__floats2half2_rn(vt.y, vp.y), __hmul2(s1, invv));
        __half2 q2 = __hsub2(__floats2half2_rn(vt.z, vp.z), __hmul2(s2, invv));
        __half2 q3 = __hsub2(__floats2half2_rn(vt.w, vp.w), __hmul2(s3, invv));
        uint4 u;
        u.x = *(unsigned*)&q0; u.y = *(unsigned*)&q1;
        u.z = *(unsigned*)&q2; u.w = *(unsigned*)&q3;
        *(uint4*)(Pair + a) = u;
    }
}

// ===========================================================================
// K3: per-plane W+H box sums of (tc*pc, tc^2, pc^2) from interleaved pairs.
// Writes SA -> g_h[0], SB -> g_h[1], SC -> g_h[4] (overwrites consumed sums).
// smem: sCt/sCp half[56][168] + sW fp32[56][160] = 73472 B.
// ===========================================================================
__global__ __launch_bounds__(NT1, 3)
void k_prodwh() {
    extern __shared__ float sm[];
    __half* sCt = (__half*)sm;
    __half* sCp = sCt + CHH * RSTR;
    float*  sW  = sm + (2 * CHH * RSTR) / 2;

    const int tx = threadIdx.x, ty = threadIdx.y;
    const int tid = ty * 160 + tx;
    const int h0c = blockIdx.x * CHO;
    const long pl = (long)blockIdx.z * DHW + (long)blockIdx.y * HW;
    const __half2* __restrict__ Pair = (const __half2*)g_h[2];

    for (int u = tid; u < CHH * 40; u += NT1) {
        int row = u / 40, c4 = u % 40;
        int gh = clampi(h0c - 4 + row, 0, Hh - 1);
        const long a = pl + (long)gh * Ww + c4 * 4;
        uint4 uu = *(const uint4*)(Pair + a);
        __half2 q0 = *reinterpret_cast<__half2*>(&uu.x);
        __half2 q1 = *reinterpret_cast<__half2*>(&uu.y);
        __half2 q2 = *reinterpret_cast<__half2*>(&uu.z);
        __half2 q3 = *reinterpret_cast<__half2*>(&uu.w);
        __half2 t01 = __lows2half2(q0, q1),  t23 = __lows2half2(q2, q3);
        __half2 p01 = __highs2half2(q0, q1), p23 = __highs2half2(q2, q3);
        uint2 ut, up;
        ut.x = *(unsigned*)&t01; ut.y = *(unsigned*)&t23;
        up.x = *(unsigned*)&p01; up.y = *(unsigned*)&p23;
        *(uint2*)(sCt + row * RSTR + 4 + c4 * 4) = ut;
        *(uint2*)(sCp + row * RSTR + 4 + c4 * 4) = up;
    }
    if (tid < CHH * 2) {
        int row = tid >> 1, side = tid & 1;
        int gh = clampi(h0c - 4 + row, 0, Hh - 1);
        const long a = pl + (long)gh * Ww + (side ? Ww - 1 : 0);
        __half2 q = Pair[a];
        __half vt = __low2half(q), vp = __high2half(q);
        __half* e0 = sCt + row * RSTR + (side ? 164 : 0);
        __half* e1 = sCp + row * RSTR + (side ? 164 : 0);
        e0[0] = vt; e0[1] = vt; e0[2] = vt; e0[3] = vt;
        e1[0] = vp; e1[1] = vp; e1[2] = vp; e1[3] = vp;
    }
    __syncthreads();

#pragma unroll
    for (int q = 0; q < 3; ++q) {
        __half* __restrict__ dst = g_h[q == 0 ? 0 : (q == 1 ? 1 : 4)];
        for (int u = tid; u < CHH * 40; u += NT1) {
            int row = u / 40, s = u % 40;
            const __half* ra = (q == 2 ? sCp : sCt) + row * RSTR + 4 * s;
            const __half* rb = (q == 1 ? sCt : sCp) + row * RSTR + 4 * s;
            float2 a01 = __half22float2(*(const __half2*)(ra));
            float2 a23 = __half22float2(*(const __half2*)(ra + 2));
            float2 a45 = __half22float2(*(const __half2*)(ra + 4));
            float2 a67 = __half22float2(*(const __half2*)(ra + 6));
            float2 a89 = __half22float2(*(const __half2*)(ra + 8));
            float2 aAB = __half22float2(*(const __half2*)(ra + 10));
            float2 b01 = __half22float2(*(const __half2*)(rb));
            float2 b23 = __half22float2(*(const __half2*)(rb + 2));
            float2 b45 = __half22float2(*(const __half2*)(rb + 4));
            float2 b67 = __half22float2(*(const __half2*)(rb + 6));
            float2 b89 = __half22float2(*(const __half2*)(rb + 8));
            float2 bAB = __half22float2(*(const __half2*)(rb + 10));
            float v0 = a01.x * b01.x, v1 = a01.y * b01.y;
            float v2 = a23.x * b23.x, v3 = a23.y * b23.y;
            float v4 = a45.x * b45.x, v5 = a45.y * b45.y;
            float v6 = a67.x * b67.x, v7 = a67.y * b67.y;
            float v8 = a89.x * b89.x, v9 = a89.y * b89.y;
            float v10 = aAB.x * bAB.x, v11 = aAB.y * bAB.y;
            float s0 = v0 + v1 + v2 + v3 + v4 + v5 + v6 + v7 + v8;
            float s1 = s0 - v0 + v9;
            float s2 = s1 - v1 + v10;
            float s3 = s2 - v2 + v11;
            *(float4*)(sW + row * 160 + 4 * s) = make_float4(s0, s1, s2, s3);
        }
        __syncthreads();
        {
            const int r0 = ty * 12;
            const float* c = sW + tx;
            float s = c[(r0 + 0) * 160] + c[(r0 + 1) * 160] + c[(r0 + 2) * 160]
                    + c[(r0 + 3) * 160] + c[(r0 + 4) * 160] + c[(r0 + 5) * 160]
                    + c[(r0 + 6) * 160] + c[(r0 + 7) * 160] + c[(r0 + 8) * 160];
            __half* o = dst + pl + (long)(h0c + r0) * Ww + tx;
            o[0] = __float2half_rn(s);
#pragma unroll
            for (int k = 1; k < 12; ++k) {
                s += c[(r0 + k + 8) * 160] - c[(r0 + k - 1) * 160];
                o[(long)k * Ww] = __float2half_rn(s);
            }
        }
        __syncthreads();
    }
}

// ===========================================================================
// K4: D-axis running box sums of SA,SB,SC in half2 arithmetic + cc (fp32) +
// mean reduction. 4 columns/thread. grid (60, 8, 2) = 960 blocks of 128.
// ===========================================================================
__global__ __launch_bounds__(128, 8)
void k_d3cc(float* __restrict__ out) {
    const int b = blockIdx.z;
    const int hw = (blockIdx.x * 128 + threadIdx.x) * 4;
    const int d0 = blockIdx.y * CD2;
    const __half* __restrict__ A = g_h[0];
    const __half* __restrict__ B = g_h[1];
    const __half* __restrict__ C = g_h[4];
    const long base = (long)b * DHW + hw;

    __half2 sa0 = __float2half2_rn(0.f), sa1 = sa0;
    __half2 sb0 = sa0, sb1 = sa0, sc0 = sa0, sc1 = sa0;
#pragma unroll
    for (int j = -4; j <= 4; ++j) {
        long a = base + (long)clampi(d0 + j, 0, Dd - 1) * HW;
        uint2 ua = *(const uint2*)(A + a);
        uint2 ub = *(const uint2*)(B + a);
        uint2 uc = *(const uint2*)(C + a);
        sa0 = __hadd2(sa0, *reinterpret_cast<__half2*>(&ua.x));
        sa1 = __hadd2(sa1, *reinterpret_cast<__half2*>(&ua.y));
        sb0 = __hadd2(sb0, *reinterpret_cast<__half2*>(&ub.x));
        sb1 = __hadd2(sb1, *reinterpret_cast<__half2*>(&ub.y));
        sc0 = __hadd2(sc0, *reinterpret_cast<__half2*>(&uc.x));
        sc1 = __hadd2(sc1, *reinterpret_cast<__half2*>(&uc.y));
    }
    float acc;
    {
        float2 fa0 = __half22float2(sa0), fa1 = __half22float2(sa1);
        float2 fb0 = __half22float2(sb0), fb1 = __half22float2(sb1);
        float2 fc0 = __half22float2(sc0), fc1 = __half22float2(sc1);
        acc = fminf(fmaxf(__fdividef(fa0.x * fa0.x + EPSL, fb0.x * fc0.x + EPSL), 0.f), 1.f)
            + fminf(fmaxf(__fdividef(fa0.y * fa0.y + EPSL, fb0.y * fc0.y + EPSL), 0.f), 1.f)
            + fminf(fmaxf(__fdividef(fa1.x * fa1.x + EPSL, fb1.x * fc1.x + EPSL), 0.f), 1.f)
            + fminf(fmaxf(__fdividef(fa1.y * fa1.y + EPSL, fb1.y * fc1.y + EPSL), 0.f), 1.f);
    }
#pragma unroll 4
    for (int d = d0 + 1; d < d0 + CD2; ++d) {
        long ap = base + (long)min(d + 4, Dd - 1) * HW;
        long am = base + (long)max(d - 5, 0) * HW;
        uint2 uap = *(const uint2*)(A + ap), uam = *(const uint2*)(A + am);
        uint2 ubp = *(const uint2*)(B + ap), ubm = *(const uint2*)(B + am);
        uint2 ucp = *(const uint2*)(C + ap), ucm = *(const uint2*)(C + am);
        sa0 = __hadd2(sa0, __hsub2(*reinterpret_cast<__half2*>(&uap.x),
                                   *reinterpret_cast<__half2*>(&uam.x)));
        sa1 = __hadd2(sa1, __hsub2(*reinterpret_cast<__half2*>(&uap.y),
                                   *reinterpret_cast<__half2*>(&uam.y)));
        sb0 = __hadd2(sb0, __hsub2(*reinterpret_cast<__half2*>(&ubp.x),
                                   *reinterpret_cast<__half2*>(&ubm.x)));
        sb1 = __hadd2(sb1, __hsub2(*reinterpret_cast<__half2*>(&ubp.y),
                                   *reinterpret_cast<__half2*>(&ubm.y)));
        sc0 = __hadd2(sc0, __hsub2(*reinterpret_cast<__half2*>(&ucp.x),
                                   *reinterpret_cast<__half2*>(&ucm.x)));
        sc1 = __hadd2(sc1, __hsub2(*reinterpret_cast<__half2*>(&ucp.y),
                                   *reinterpret_cast<__half2*>(&ucm.y)));
        float2 fa0 = __half22float2(sa0), fa1 = __half22float2(sa1);
        float2 fb0 = __half22float2(sb0), fb1 = __half22float2(sb1);
        float2 fc0 = __half22float2(sc0), fc1 = __half22float2(sc1);
        acc += fminf(fmaxf(__fdividef(fa0.x * fa0.x + EPSL, fb0.x * fc0.x + EPSL), 0.f), 1.f)
             + fminf(fmaxf(__fdividef(fa0.y * fa0.y + EPSL, fb0.y * fc0.y + EPSL), 0.f), 1.f)
             + fminf(fmaxf(__fdividef(fa1.x * fa1.x + EPSL, fb1.x * fc1.x + EPSL), 0.f), 1.f)
             + fminf(fmaxf(__fdividef(fa1.y * fa1.y + EPSL, fb1.y * fc1.y + EPSL), 0.f), 1.f);
    }

    __shared__ float red[128];
    red[threadIdx.x] = acc;
    __syncthreads();
#pragma unroll
    for (int s = 64; s > 0; s >>= 1) {
        if (threadIdx.x < s) red[threadIdx.x] += red[threadIdx.x + s];
        __syncthreads();
    }
    if (threadIdx.x == 0) atomicAdd(out, -red[0] * (1.0f / (float)NTOT));
}

// ===========================================================================
extern "C" void kernel_launch(void* const* d_in, const int* in_sizes, int n_in,
                              void* d_out, int out_size) {
    const float* t = (const float*)d_in[0];  // y_true
    const float* p = (const float*)d_in[1];  // y_pred
    float* out = (float*)d_out;

    static const int SMWH = (CHH * RSTR + CHH * 160) * 4;   // 73472 B
    cudaFuncSetAttribute(k_wh2,    cudaFuncAttributeMaxDynamicSharedMemorySize, SMWH);
    cudaFuncSetAttribute(k_prodwh, cudaFuncAttributeMaxDynamicSharedMemorySize, SMWH);

    const dim3 bwh(160, 4);
    const dim3 gwh(Hh / CHO, Dd, Bsz);               // (4, 160, 2)
    const dim3 gcol(HW / 512, Dd / CD2, Bsz);        // (60, 8, 2) = 960 blocks

    k_wh2<<<gwh, bwh, SMWH>>>(t, p, out);
    k_dcenter<<<gcol, 128>>>(t, p);
    k_prodwh<<<gwh, bwh, SMWH>>>();
    k_d3cc<<<gcol, 128>>>(out);
}

// round 14
// speedup vs baseline: 1.0616x; 1.0335x over previous
#include <cuda_runtime.h>
#include <cuda_fp16.h>

// Geometry: [B=2, C=1, D=160, H=192, W=160] fp32.
#define Bsz 2
#define Dd  160
#define Hh  192
#define Ww  160
#define HW  (Hh * Ww)
#define DHW (Dd * HW)
#define NTOT (Bsz * DHW)
#define INV_V (1.0f / 729.0f)
#define EPSL 1e-6f

// WH tiling: full W rows, CHO output H-rows (+8 halo), padded row stride.
#define CHO 48
#define CHH 56          // CHO + 8
#define RSTR 168        // 4 + 160 + 4
#define NT1 640         // blockDim (160, 4)

#define CD2 20          // D-chunk for column kernels (960 blocks)

// Half intermediates: [0..1]=interleaved (St,Sp) sum pairs -> later (SA,SB)
// product-pair field; [2..3]=interleaved (tc,pc) pairs; [4]=SC.  98.3 MB.
__device__ __half g_h[5][NTOT];

__device__ __forceinline__ int clampi(int v, int lo, int hi) {
    return min(max(v, lo), hi);
}

// ===========================================================================
// K1: per-plane W+H 9x9 box sums of (t,p) carried as interleaved half2 pairs.
// Output: paired (St,Sp) half2 stream in g_h[0..1]. Zeroes the out scalar.
// smem: sIn half2[56][168] + sW half2[56][160] = 73472 B.
// ===========================================================================
__global__ __launch_bounds__(NT1, 3)
void k_wh2(const float* __restrict__ t, const float* __restrict__ p,
           float* __restrict__ out) {
    extern __shared__ float sm[];
    __half2* sIn = (__half2*)sm;
    __half2* sW  = sIn + CHH * RSTR;

    const int tx = threadIdx.x, ty = threadIdx.y;
    const int tid = ty * 160 + tx;
    if (blockIdx.x == 0 && blockIdx.y == 0 && blockIdx.z == 0 && tid == 0)
        *out = 0.f;
    const int h0c = blockIdx.x * CHO;
    const long pl = (long)blockIdx.z * DHW + (long)blockIdx.y * HW;
    __half2* __restrict__ SumPair = (__half2*)g_h[0];

    for (int u = tid; u < CHH * 40; u += NT1) {
        int row = u / 40, c4 = u % 40;
        int gh = clampi(h0c - 4 + row, 0, Hh - 1);
        const long a = pl + (long)gh * Ww + c4 * 4;
        float4 vt = *(const float4*)(t + a);
        float4 vp = *(const float4*)(p + a);
        __half2 q0 = __floats2half2_rn(vt.x, vp.x);
        __half2 q1 = __floats2half2_rn(vt.y, vp.y);
        __half2 q2 = __floats2half2_rn(vt.z, vp.z);
        __half2 q3 = __floats2half2_rn(vt.w, vp.w);
        uint4 u4;
        u4.x = *(unsigned*)&q0; u4.y = *(unsigned*)&q1;
        u4.z = *(unsigned*)&q2; u4.w = *(unsigned*)&q3;
        *(uint4*)(sIn + row * RSTR + 4 + c4 * 4) = u4;
    }
    if (tid < CHH * 2) {
        int row = tid >> 1, side = tid & 1;
        int gh = clampi(h0c - 4 + row, 0, Hh - 1);
        const long a = pl + (long)gh * Ww + (side ? Ww - 1 : 0);
        __half2 q = __floats2half2_rn(t[a], p[a]);
        __half2* e = sIn + row * RSTR + (side ? 164 : 0);
        e[0] = q; e[1] = q; e[2] = q; e[3] = q;
    }
    __syncthreads();

    for (int u = tid; u < CHH * 40; u += NT1) {
        int row = u / 40, s = u % 40;
        const __half2* rp = sIn + row * RSTR + 4 * s;
        uint4 x0 = *(const uint4*)(rp);
        uint4 x1 = *(const uint4*)(rp + 4);
        uint4 x2 = *(const uint4*)(rp + 8);
        float2 f0 = __half22float2(*reinterpret_cast<__half2*>(&x0.x));
        float2 f1 = __half22float2(*reinterpret_cast<__half2*>(&x0.y));
        float2 f2 = __half22float2(*reinterpret_cast<__half2*>(&x0.z));
        float2 f3 = __half22float2(*reinterpret_cast<__half2*>(&x0.w));
        float2 f4 = __half22float2(*reinterpret_cast<__half2*>(&x1.x));
        float2 f5 = __half22float2(*reinterpret_cast<__half2*>(&x1.y));
        float2 f6 = __half22float2(*reinterpret_cast<__half2*>(&x1.z));
        float2 f7 = __half22float2(*reinterpret_cast<__half2*>(&x1.w));
        float2 f8 = __half22float2(*reinterpret_cast<__half2*>(&x2.x));
        float2 f9 = __half22float2(*reinterpret_cast<__half2*>(&x2.y));
        float2 fA = __half22float2(*reinterpret_cast<__half2*>(&x2.z));
        float2 fB = __half22float2(*reinterpret_cast<__half2*>(&x2.w));
        float2 s0, s1, s2, s3;
        s0.x = f0.x + f1.x + f2.x + f3.x + f4.x + f5.x + f6.x + f7.x + f8.x;
        s0.y = f0.y + f1.y + f2.y + f3.y + f4.y + f5.y + f6.y + f7.y + f8.y;
        s1.x = s0.x - f0.x + f9.x;  s1.y = s0.y - f0.y + f9.y;
        s2.x = s1.x - f1.x + fA.x;  s2.y = s1.y - f1.y + fA.y;
        s3.x = s2.x - f2.x + fB.x;  s3.y = s2.y - f2.y + fB.y;
        __half2 w0 = __floats2half2_rn(s0.x, s0.y);
        __half2 w1 = __floats2half2_rn(s1.x, s1.y);
        __half2 w2 = __floats2half2_rn(s2.x, s2.y);
        __half2 w3 = __floats2half2_rn(s3.x, s3.y);
        uint4 u4;
        u4.x = *(unsigned*)&w0; u4.y = *(unsigned*)&w1;
        u4.z = *(unsigned*)&w2; u4.w = *(unsigned*)&w3;
        *(uint4*)(sW + row * 160 + 4 * s) = u4;
    }
    __syncthreads();

    {
        const int r0 = ty * 12;
        const __half2* c = sW + tx;
        float2 s = make_float2(0.f, 0.f);
#pragma unroll
        for (int k = 0; k < 9; ++k) {
            float2 f = __half22float2(c[(r0 + k) * 160]);
            s.x += f.x; s.y += f.y;
        }
        __half2* o = SumPair + pl + (long)(h0c + r0) * Ww + tx;
        o[0] = __floats2half2_rn(s.x, s.y);
#pragma unroll
        for (int k = 1; k < 12; ++k) {
            float2 fp2 = __half22float2(c[(r0 + k + 8) * 160]);
            float2 fm2 = __half22float2(c[(r0 + k - 1) * 160]);
            s.x += fp2.x - fm2.x; s.y += fp2.y - fm2.y;
            o[(long)k * Ww] = __floats2half2_rn(s.x, s.y);
        }
    }
}

// ===========================================================================
// K2: D-axis running box sum of (St,Sp) pairs in half2; fused centering ->
// interleaved (tc,pc) pairs. 4 columns/thread. grid (60, 8, 2).
// ===========================================================================
__global__ __launch_bounds__(128, 8)
void k_dcenter(const float* __restrict__ t, const float* __restrict__ p) {
    const int b = blockIdx.z;
    const int hw = (blockIdx.x * 128 + threadIdx.x) * 4;
    const int d0 = blockIdx.y * CD2;
    const __half2* __restrict__ Sum = (const __half2*)g_h[0];
    __half2* __restrict__ Pair = (__half2*)g_h[2];
    const long base = (long)b * DHW + hw;

    __half2 s0 = __float2half2_rn(0.f), s1 = s0, s2 = s0, s3 = s0;
#pragma unroll
    for (int j = -4; j <= 4; ++j) {
        long a = base + (long)clampi(d0 + j, 0, Dd - 1) * HW;
        uint4 u = *(const uint4*)(Sum + a);
        s0 = __hadd2(s0, *reinterpret_cast<__half2*>(&u.x));
        s1 = __hadd2(s1, *reinterpret_cast<__half2*>(&u.y));
        s2 = __hadd2(s2, *reinterpret_cast<__half2*>(&u.z));
        s3 = __hadd2(s3, *reinterpret_cast<__half2*>(&u.w));
    }
    const __half2 invv = __float2half2_rn(INV_V);
    {
        long a = base + (long)d0 * HW;
        float4 vt = *(const float4*)(t + a);
        float4 vp = *(const float4*)(p + a);
        __half2 q0 = __hsub2(__floats2half2_rn(vt.x, vp.x), __hmul2(s0, invv));
        __half2 q1 = __hsub2(__floats2half2_rn(vt.y, vp.y), __hmul2(s1, invv));
        __half2 q2 = __hsub2(__floats2half2_rn(vt.z, vp.z), __hmul2(s2, invv));
        __half2 q3 = __hsub2(__floats2half2_rn(vt.w, vp.w), __hmul2(s3, invv));
        uint4 u;
        u.x = *(unsigned*)&q0; u.y = *(unsigned*)&q1;
        u.z = *(unsigned*)&q2; u.w = *(unsigned*)&q3;
        *(uint4*)(Pair + a) = u;
    }
#pragma unroll 4
    for (int d = d0 + 1; d < d0 + CD2; ++d) {
        long ap = base + (long)min(d + 4, Dd - 1) * HW;
        long am = base + (long)max(d - 5, 0) * HW;
        uint4 ue = *(const uint4*)(Sum + ap);
        uint4 ul = *(const uint4*)(Sum + am);
        s0 = __hadd2(s0, __hsub2(*reinterpret_cast<__half2*>(&ue.x),
                                 *reinterpret_cast<__half2*>(&ul.x)));
        s1 = __hadd2(s1, __hsub2(*reinterpret_cast<__half2*>(&ue.y),
                                 *reinterpret_cast<__half2*>(&ul.y)));
        s2 = __hadd2(s2, __hsub2(*reinterpret_cast<__half2*>(&ue.z),
                                 *reinterpret_cast<__half2*>(&ul.z)));
        s3 = __hadd2(s3, __hsub2(*reinterpret_cast<__half2*>(&ue.w),
                                 *reinterpret_cast<__half2*>(&ul.w)));
        long a = base + (long)d * HW;
        float4 vt = *(const float4*)(t + a);
        float4 vp = *(const float4*)(p + a);
        __half2 q0 = __hsub2(__floats2half2_rn(vt.x, vp.x), __hmul2(s0, invv));
        __half2 q1 = __hsub2(__floats2half2_rn(vt.y, vp.y), __hmul2(s1, invv));
        __half2 q2 = __hsub2(__floats2half2_rn(vt.z, vp.z), __hmul2(s2, invv));
        __half2 q3 = __hsub2(__floats2half2_rn(vt.w, vp.w), __hmul2(s3, invv));
        uint4 u;
        u.x = *(unsigned*)&q0; u.y = *(unsigned*)&q1;
        u.z = *(unsigned*)&q2; u.w = *(unsigned*)&q3;
        *(uint4*)(Pair + a) = u;
    }
}

// ===========================================================================
// K3: per-plane W+H box sums, 2 passes:
//  pass AB: paired products (tc*pc, tc*tc) -> interleaved (SA,SB) half2
//           field in g_h[0..1];
//  pass C : pc*pc -> g_h[4].
// smem: sCt/sCp half[56][168] + sW (half2 or fp32)[56][160] = 73472 B.
// ===========================================================================
__global__ __launch_bounds__(NT1, 3)
void k_prodwh() {
    extern __shared__ float sm[];
    __half* sCt = (__half*)sm;
    __half* sCp = sCt + CHH * RSTR;
    __half2* sWab = (__half2*)(sm + (2 * CHH * RSTR) / 2);
    float*   sWc  = sm + (2 * CHH * RSTR) / 2;

    const int tx = threadIdx.x, ty = threadIdx.y;
    const int tid = ty * 160 + tx;
    const int h0c = blockIdx.x * CHO;
    const long pl = (long)blockIdx.z * DHW + (long)blockIdx.y * HW;
    const __half2* __restrict__ Pair = (const __half2*)g_h[2];
    __half2* __restrict__ ABout = (__half2*)g_h[0];

    // ---- load interleaved pairs, deinterleave into smem ----
    for (int u = tid; u < CHH * 40; u += NT1) {
        int row = u / 40, c4 = u % 40;
        int gh = clampi(h0c - 4 + row, 0, Hh - 1);
        const long a = pl + (long)gh * Ww + c4 * 4;
        uint4 uu = *(const uint4*)(Pair + a);
        __half2 q0 = *reinterpret_cast<__half2*>(&uu.x);
        __half2 q1 = *reinterpret_cast<__half2*>(&uu.y);
        __half2 q2 = *reinterpret_cast<__half2*>(&uu.z);
        __half2 q3 = *reinterpret_cast<__half2*>(&uu.w);
        __half2 t01 = __lows2half2(q0, q1),  t23 = __lows2half2(q2, q3);
        __half2 p01 = __highs2half2(q0, q1), p23 = __highs2half2(q2, q3);
        uint2 ut, up;
        ut.x = *(unsigned*)&t01; ut.y = *(unsigned*)&t23;
        up.x = *(unsigned*)&p01; up.y = *(unsigned*)&p23;
        *(uint2*)(sCt + row * RSTR + 4 + c4 * 4) = ut;
        *(uint2*)(sCp + row * RSTR + 4 + c4 * 4) = up;
    }
    if (tid < CHH * 2) {
        int row = tid >> 1, side = tid & 1;
        int gh = clampi(h0c - 4 + row, 0, Hh - 1);
        const long a = pl + (long)gh * Ww + (side ? Ww - 1 : 0);
        __half2 q = Pair[a];
        __half vt = __low2half(q), vp = __high2half(q);
        __half* e0 = sCt + row * RSTR + (side ? 164 : 0);
        __half* e1 = sCp + row * RSTR + (side ? 164 : 0);
        e0[0] = vt; e0[1] = vt; e0[2] = vt; e0[3] = vt;
        e1[0] = vp; e1[1] = vp; e1[2] = vp; e1[3] = vp;
    }
    __syncthreads();

    // ---- pass AB: W strip sums of paired products (A=tc*pc, B=tc*tc) ----
    for (int u = tid; u < CHH * 40; u += NT1) {
        int row = u / 40, s = u % 40;
        const __half2* ra = (const __half2*)(sCt + row * RSTR + 4 * s);
        const __half2* rb = (const __half2*)(sCp + row * RSTR + 4 * s);
        float2 ab[12];
#pragma unroll
        for (int i = 0; i < 6; ++i) {
            __half2 ti = ra[i], pi = rb[i];
            __half2 lo = __hmul2(__low2half2(ti),  __lows2half2(pi, ti));
            __half2 hi = __hmul2(__high2half2(ti), __highs2half2(pi, ti));
            ab[2 * i]     = __half22float2(lo);
            ab[2 * i + 1] = __half22float2(hi);
        }
        float2 s0, s1, s2, s3;
        s0.x = ab[0].x + ab[1].x + ab[2].x + ab[3].x + ab[4].x
             + ab[5].x + ab[6].x + ab[7].x + ab[8].x;
        s0.y = ab[0].y + ab[1].y + ab[2].y + ab[3].y + ab[4].y
             + ab[5].y + ab[6].y + ab[7].y + ab[8].y;
        s1.x = s0.x - ab[0].x + ab[9].x;  s1.y = s0.y - ab[0].y + ab[9].y;
        s2.x = s1.x - ab[1].x + ab[10].x; s2.y = s1.y - ab[1].y + ab[10].y;
        s3.x = s2.x - ab[2].x + ab[11].x; s3.y = s2.y - ab[2].y + ab[11].y;
        __half2 w0 = __floats2half2_rn(s0.x, s0.y);
        __half2 w1 = __floats2half2_rn(s1.x, s1.y);
        __half2 w2 = __floats2half2_rn(s2.x, s2.y);
        __half2 w3 = __floats2half2_rn(s3.x, s3.y);
        uint4 u4;
        u4.x = *(unsigned*)&w0; u4.y = *(unsigned*)&w1;
        u4.z = *(unsigned*)&w2; u4.w = *(unsigned*)&w3;
        *(uint4*)(sWab + row * 160 + 4 * s) = u4;
    }
    __syncthreads();
    // ---- pass AB: H running sums, store (SA,SB) pairs ----
    {
        const int r0 = ty * 12;
        const __half2* c = sWab + tx;
        float2 s = make_float2(0.f, 0.f);
#pragma unroll
        for (int k = 0; k < 9; ++k) {
            float2 f = __half22float2(c[(r0 + k) * 160]);
            s.x += f.x; s.y += f.y;
        }
        __half2* o = ABout + pl + (long)(h0c + r0) * Ww + tx;
        o[0] = __floats2half2_rn(s.x, s.y);
#pragma unroll
        for (int k = 1; k < 12; ++k) {
            float2 fp2 = __half22float2(c[(r0 + k + 8) * 160]);
            float2 fm2 = __half22float2(c[(r0 + k - 1) * 160]);
            s.x += fp2.x - fm2.x; s.y += fp2.y - fm2.y;
            o[(long)k * Ww] = __floats2half2_rn(s.x, s.y);
        }
    }
    __syncthreads();

    // ---- pass C: W strip sums of pc*pc ----
    for (int u = tid; u < CHH * 40; u += NT1) {
        int row = u / 40, s = u % 40;
        const __half2* rb = (const __half2*)(sCp + row * RSTR + 4 * s);
        float f[12];
#pragma unroll
        for (int i = 0; i < 6; ++i) {
            __half2 pi = rb[i];
            float2 sq = __half22float2(__hmul2(pi, pi));
            f[2 * i] = sq.x; f[2 * i + 1] = sq.y;
        }
        float s0 = f[0] + f[1] + f[2] + f[3] + f[4] + f[5] + f[6] + f[7] + f[8];
        float s1 = s0 - f[0] + f[9];
        float s2 = s1 - f[1] + f[10];
        float s3 = s2 - f[2] + f[11];
        *(float4*)(sWc + row * 160 + 4 * s) = make_float4(s0, s1, s2, s3);
    }
    __syncthreads();
    // ---- pass C: H running sums, store SC ----
    {
        const int r0 = ty * 12;
        const float* c = sWc + tx;
        float s = c[(r0 + 0) * 160] + c[(r0 + 1) * 160] + c[(r0 + 2) * 160]
                + c[(r0 + 3) * 160] + c[(r0 + 4) * 160] + c[(r0 + 5) * 160]
                + c[(r0 + 6) * 160] + c[(r0 + 7) * 160] + c[(r0 + 8) * 160];
        __half* o = g_h[4] + pl + (long)(h0c + r0) * Ww + tx;
        o[0] = __float2half_rn(s);
#pragma unroll
        for (int k = 1; k < 12; ++k) {
            s += c[(r0 + k + 8) * 160] - c[(r0 + k - 1) * 160];
            o[(long)k * Ww] = __float2half_rn(s);
        }
    }
}

// ===========================================================================
// K4: D-axis running box sums of (SA,SB) pairs + SC in half2 + cc (fp32) +
// mean reduction. 4 voxels/thread, 2 load streams. grid (60, 8, 2).
// ===========================================================================
__global__ __launch_bounds__(128, 8)
void k_d3cc(float* __restrict__ out) {
    const int b = blockIdx.z;
    const int hw = (blockIdx.x * 128 + threadIdx.x) * 4;
    const int d0 = blockIdx.y * CD2;
    const __half2* __restrict__ AB = (const __half2*)g_h[0];
    const __half* __restrict__ C = g_h[4];
    const long base = (long)b * DHW + hw;

    __half2 s0 = __float2half2_rn(0.f), s1 = s0, s2 = s0, s3 = s0;
    __half2 c0 = s0, c1 = s0;
#pragma unroll
    for (int j = -4; j <= 4; ++j) {
        long a = base + (long)clampi(d0 + j, 0, Dd - 1) * HW;
        uint4 u = *(const uint4*)(AB + a);
        uint2 v = *(const uint2*)(C + a);
        s0 = __hadd2(s0, *reinterpret_cast<__half2*>(&u.x));
        s1 = __hadd2(s1, *reinterpret_cast<__half2*>(&u.y));
        s2 = __hadd2(s2, *reinterpret_cast<__half2*>(&u.z));
        s3 = __hadd2(s3, *reinterpret_cast<__half2*>(&u.w));
        c0 = __hadd2(c0, *reinterpret_cast<__half2*>(&v.x));
        c1 = __hadd2(c1, *reinterpret_cast<__half2*>(&v.y));
    }
    float acc;
    {
        float2 f0 = __half22float2(s0), f1 = __half22float2(s1);
        float2 f2 = __half22float2(s2), f3 = __half22float2(s3);
        float2 g0 = __half22float2(c0), g1 = __half22float2(c1);
        acc = fminf(fmaxf(__fdividef(f0.x * f0.x + EPSL, f0.y * g0.x + EPSL), 0.f), 1.f)
            + fminf(fmaxf(__fdividef(f1.x * f1.x + EPSL, f1.y * g0.y + EPSL), 0.f), 1.f)
            + fminf(fmaxf(__fdividef(f2.x * f2.x + EPSL, f2.y * g1.x + EPSL), 0.f), 1.f)
            + fminf(fmaxf(__fdividef(f3.x * f3.x + EPSL, f3.y * g1.y + EPSL), 0.f), 1.f);
    }
#pragma unroll 4
    for (int d = d0 + 1; d < d0 + CD2; ++d) {
        long ap = base + (long)min(d + 4, Dd - 1) * HW;
        long am = base + (long)max(d - 5, 0) * HW;
        uint4 ue = *(const uint4*)(AB + ap), ul = *(const uint4*)(AB + am);
        uint2 ve = *(const uint2*)(C + ap),  vl = *(const uint2*)(C + am);
        s0 = __hadd2(s0, __hsub2(*reinterpret_cast<__half2*>(&ue.x),
                                 *reinterpret_cast<__half2*>(&ul.x)));
        s1 = __hadd2(s1, __hsub2(*reinterpret_cast<__half2*>(&ue.y),
                                 *reinterpret_cast<__half2*>(&ul.y)));
        s2 = __hadd2(s2, __hsub2(*reinterpret_cast<__half2*>(&ue.z),
                                 *reinterpret_cast<__half2*>(&ul.z)));
        s3 = __hadd2(s3, __hsub2(*reinterpret_cast<__half2*>(&ue.w),
                                 *reinterpret_cast<__half2*>(&ul.w)));
        c0 = __hadd2(c0, __hsub2(*reinterpret_cast<__half2*>(&ve.x),
                                 *reinterpret_cast<__half2*>(&vl.x)));
        c1 = __hadd2(c1, __hsub2(*reinterpret_cast<__half2*>(&ve.y),
                                 *reinterpret_cast<__half2*>(&vl.y)));
        float2 f0 = __half22float2(s0), f1 = __half22float2(s1);
        float2 f2 = __half22float2(s2), f3 = __half22float2(s3);
        float2 g0 = __half22float2(c0), g1 = __half22float2(c1);
        acc += fminf(fmaxf(__fdividef(f0.x * f0.x + EPSL, f0.y * g0.x + EPSL), 0.f), 1.f)
             + fminf(fmaxf(__fdividef(f1.x * f1.x + EPSL, f1.y * g0.y + EPSL), 0.f), 1.f)
             + fminf(fmaxf(__fdividef(f2.x * f2.x + EPSL, f2.y * g1.x + EPSL), 0.f), 1.f)
             + fminf(fmaxf(__fdividef(f3.x * f3.x + EPSL, f3.y * g1.y + EPSL), 0.f), 1.f);
    }

    __shared__ float red[128];
    red[threadIdx.x] = acc;
    __syncthreads();
#pragma unroll
    for (int s = 64; s > 0; s >>= 1) {
        if (threadIdx.x < s) red[threadIdx.x] += red[threadIdx.x + s];
        __syncthreads();
    }
    if (threadIdx.x == 0) atomicAdd(out, -red[0] * (1.0f / (float)NTOT));
}

// ===========================================================================
extern "C" void kernel_launch(void* const* d_in, const int* in_sizes, int n_in,
                              void* d_out, int out_size) {
    const float* t = (const float*)d_in[0];  // y_true
    const float* p = (const float*)d_in[1];  // y_pred
    float* out = (float*)d_out;

    static const int SMWH = (CHH * RSTR + CHH * 160) * 4;   // 73472 B
    cudaFuncSetAttribute(k_wh2,    cudaFuncAttributeMaxDynamicSharedMemorySize, SMWH);
    cudaFuncSetAttribute(k_prodwh, cudaFuncAttributeMaxDynamicSharedMemorySize, SMWH);

    const dim3 bwh(160, 4);
    const dim3 gwh(Hh / CHO, Dd, Bsz);               // (4, 160, 2)
    const dim3 gcol(HW / 512, Dd / CD2, Bsz);        // (60, 8, 2) = 960 blocks

    k_wh2<<<gwh, bwh, SMWH>>>(t, p, out);
    k_dcenter<<<gcol, 128>>>(t, p);
    k_prodwh<<<gwh, bwh, SMWH>>>();
    k_d3cc<<<gcol, 128>>>(out);
}